// round 17
// baseline (speedup 1.0000x reference)
#include <cuda_runtime.h>
#include <cuda_bf16.h>

#define DD 1024
#define HH 1024
#define BB 8192

__device__ __align__(16) float g_twTab[DD * HH]; // NEGATED: -tanh(W[h][d]/2)
__device__ unsigned            g_xb[BB * 32];    // packed x bits [b][d/32]
__device__ __align__(16) float g_tinit[HH];      // tanh(c[h]/2)
__device__ __align__(16) float g_B2[DD];         // b[d] + 0.5*rowsum(V[d])

typedef unsigned long long u64;

__device__ __forceinline__ u64 fma2_(u64 a, u64 b, u64 c) {
    u64 d; asm("fma.rn.f32x2 %0, %1, %2, %3;" : "=l"(d) : "l"(a), "l"(b), "l"(c)); return d;
}
__device__ __forceinline__ u64 mul2_(u64 a, u64 b) {
    u64 d; asm("mul.rn.f32x2 %0, %1, %2;" : "=l"(d) : "l"(a), "l"(b)); return d;
}
__device__ __forceinline__ u64 add2_(u64 a, u64 b) {
    u64 d; asm("add.rn.f32x2 %0, %1, %2;" : "=l"(d) : "l"(a), "l"(b)); return d;
}
__device__ __forceinline__ float frcp_(float x) {
    float r; asm("rcp.approx.f32 %0, %1;" : "=f"(r) : "f"(x)); return r;
}
__device__ __forceinline__ float fex2_(float x) {
    float r; asm("ex2.approx.f32 %0, %1;" : "=f"(r) : "f"(x)); return r;
}
__device__ __forceinline__ void unpack2_(u64 u, float& a, float& b) {
    asm("mov.b64 {%0, %1}, %2;" : "=f"(a), "=f"(b) : "l"(u));
}
__device__ __forceinline__ float sigm_(float t) {
    return frcp_(1.0f + fex2_(-1.4426950408889634f * t));
}

#define ONE2  0x3f8000003f800000ULL
#define MONE2 0xbf800000bf800000ULL

// tanh addition law with NEGATED table (twn = -tw):
//   tau' = (tau + tw)/(1 + tau*tw);  zn = -tau*tw = tau*twn
//   1/(1+z) ~ 1 + zn + zn^2 (deg-2; err +z^3 is sign-random). 5 ops, no MUFU.
__device__ __forceinline__ void upd_(u64& tau, u64 twn) {
    u64 zn  = mul2_(tau, twn);
    u64 num = fma2_(twn, MONE2, tau);     // tau + tw
    u64 p   = add2_(ONE2, zn);
    p = fma2_(zn, p, ONE2);
    tau = mul2_(num, p);
}

// load 2 x ulonglong2 per thread = 256 floats per warp (one 256-h slice)
__device__ __forceinline__ void ldg2_(u64* dst, const float* base, int lane) {
    const ulonglong2* p = reinterpret_cast<const ulonglong2*>(base);
    #pragma unroll
    for (int q = 0; q < 2; ++q) {
        ulonglong2 v = __ldg(&p[lane + 32 * q]);
        dst[2*q] = v.x; dst[2*q+1] = v.y;
    }
}

// -------- fused precompute --------
#define NB_TW (DD * HH / 256)        // 16384
#define NB_XB (BB * DD / 256)        // 32768
#define NB_TC 4
#define NB_B2 128

__global__ void prep_all(const float* __restrict__ x, const float* __restrict__ V,
                         const float* __restrict__ bvec, const float* __restrict__ W,
                         const float* __restrict__ c) {
    const int blk = blockIdx.x;
    if (blk < NB_TW) {
        int i = blk * 256 + threadIdx.x;           // over H*D, W row-major [H][D]
        int h = i >> 10, d = i & 1023;
        g_twTab[d * HH + h] = -tanhf(0.5f * W[i]); // negated
    } else if (blk < NB_TW + NB_XB) {
        int gtid = (blk - NB_TW) * 256 + threadIdx.x;
        int warp = gtid >> 5, lane = gtid & 31;
        int b = warp >> 5, ch = warp & 31;
        float v = x[b * DD + ch * 32 + lane];
        unsigned m = __ballot_sync(0xffffffffu, v != 0.0f);
        if (lane == 0) g_xb[b * 32 + ch] = m;
    } else if (blk < NB_TW + NB_XB + NB_TC) {
        int h = (blk - NB_TW - NB_XB) * 256 + threadIdx.x;
        g_tinit[h] = tanhf(0.5f * c[h]);
    } else {
        int warp = ((blk - NB_TW - NB_XB - NB_TC) * 256 + threadIdx.x) >> 5;
        int lane = threadIdx.x & 31;
        float s = 0.0f;
        const float4* row = reinterpret_cast<const float4*>(V + warp * HH);
        #pragma unroll
        for (int q = 0; q < 8; ++q) {
            float4 v = row[lane + 32 * q];
            s += (v.x + v.y) + (v.z + v.w);
        }
        #pragma unroll
        for (int off = 16; off; off >>= 1) s += __shfl_xor_sync(0xffffffffu, s, off);
        if (lane == 0) g_B2[warp] = bvec[warp] + 0.5f * s;
    }
}

// -------- main --------
// Warp QUAD (4 warps) owns 4 batch rows; warp (wid&3) owns h-slice
// [slice*256, +256). tau state: 4 rows x 4 u64 = 32 regs. Small per-warp
// footprint -> 3 CTAs/SM (24 warps). Per 8-step block: per-lane partials ->
// padded smem; quad-scoped bar; two-stage reduction (strip sums + shfl).
#define WSTRIDE 1156   // warp smem stride in floats (1152 data + 4 bank skew)

__global__ void __launch_bounds__(256, 3)
nade_main(const float* __restrict__ V, float* __restrict__ out) {
    __shared__ float sP[8 * WSTRIDE];  // [warp][row*288 + k*36 + lane]
    const int tid = threadIdx.x, lane = tid & 31, wid = tid >> 5;
    const int quad = wid >> 2, slice = wid & 3;
    const int b0 = blockIdx.x * 8 + quad * 4;
    const int hoff = slice * 256;
    const float* TWN = &g_twTab[0];

    u64 t[4][4];
    #pragma unroll
    for (int q = 0; q < 2; ++q) {
        const u64* ti = reinterpret_cast<const u64*>(&g_tinit[hoff + (lane + 32 * q) * 4]);
        u64 lo = ti[0], hi = ti[1];
        #pragma unroll
        for (int r = 0; r < 4; ++r) { t[r][2*q] = lo; t[r][2*q+1] = hi; }
    }

    float* P = sP + wid * WSTRIDE;
    unsigned xw[4] = {0, 0, 0, 0};

    u64 v[4];
    ldg2_(v, V + hoff, lane);   // prime V row 0

    #pragma unroll 1
    for (int blk = 0; blk < 128; ++blk) {
        if ((blk & 3) == 0) {
            #pragma unroll
            for (int r = 0; r < 4; ++r)
                xw[r] = __ldg(&g_xb[(unsigned)(b0 + r) * 32 + (blk >> 2)]);
        }
        const int dbase = blk * 8;

        #pragma unroll 2
        for (int k = 0; k < 8; ++k) {
            const int d = dbase + k;
            const unsigned bit = 1u << ((blk & 3) * 8 + k);
            const bool anyupd = ((xw[0] | xw[1] | xw[2] | xw[3]) & bit) != 0u;

            // tw load FIRST: latency overlaps the independent dot below
            u64 tw[4];
            if (anyupd) ldg2_(tw, TWN + (size_t)d * HH + hoff, lane);

            // dots: 4 rows share V registers
            #pragma unroll
            for (int r = 0; r < 4; ++r) {
                u64 a0 = mul2_(t[r][0], v[0]);
                u64 a1 = mul2_(t[r][1], v[1]);
                a0 = fma2_(t[r][2], v[2], a0);
                a1 = fma2_(t[r][3], v[3], a1);
                u64 s2 = add2_(a0, a1);
                float xa, xb2; unpack2_(s2, xa, xb2);
                P[r * 288 + k * 36 + lane] = xa + xb2;
            }

            // prefetch next V row (WAR on v; overlaps the update below)
            ldg2_(v, V + (size_t)((d + 1) & (DD - 1)) * HH + hoff, lane);

            // conditional updates (warp-uniform branches)
            if (anyupd) {
                #pragma unroll
                for (int r = 0; r < 4; ++r) {
                    if (xw[r] & bit) {
                        #pragma unroll
                        for (int q = 0; q < 4; ++q) upd_(t[r][q], tw[q]);
                    }
                }
            }
        }

        asm volatile("bar.sync %0, 128;" :: "r"(quad + 1) : "memory");
        {
            // two-stage quad reduction:
            // thread handles (o = row*8+step from its warp slot, w = lane&3):
            //   o = warp_in_quad*8 + (lane>>2)  -> warp w_in_quad covers row w_in_quad? no:
            //   o enumerates 0..31 across the quad: o = slice*8 + (lane>>2)
            const int o = slice * 8 + (lane >> 2);       // 0..31
            const int row = o >> 3, step = o & 7;
            const int w = lane & 3;                      // which slice buffer
            const float* A = sP + (quad * 4 + w) * WSTRIDE + row * 288 + step * 36;
            float s = 0.0f;
            #pragma unroll
            for (int j = 0; j < 32; j += 4) {
                float4 u0 = *reinterpret_cast<const float4*>(A + j);
                s += (u0.x + u0.y) + (u0.z + u0.w);
            }
            s += __shfl_xor_sync(0xffffffffu, s, 1);
            s += __shfl_xor_sync(0xffffffffu, s, 2);
            if (w == 0) {
                const int d0 = dbase + step;
                out[(unsigned)(b0 + row) * DD + d0] = sigm_(fmaf(s, 0.5f, __ldg(&g_B2[d0])));
            }
        }
        asm volatile("bar.sync %0, 128;" :: "r"(quad + 1) : "memory");
    }
}

extern "C" void kernel_launch(void* const* d_in, const int* in_sizes, int n_in,
                              void* d_out, int out_size) {
    const float* x = (const float*)d_in[0];   // (B, D)
    const float* V = (const float*)d_in[1];   // (D, H)
    const float* b = (const float*)d_in[2];   // (D,)
    const float* W = (const float*)d_in[3];   // (H, D)
    const float* c = (const float*)d_in[4];   // (H,)
    float* out = (float*)d_out;               // (B, D)

    prep_all<<<NB_TW + NB_XB + NB_TC + NB_B2, 256>>>(x, V, b, W, c);
    nade_main<<<BB / 8, 256>>>(V, out);
}